// round 16
// baseline (speedup 1.0000x reference)
#include <cuda_runtime.h>
#include <cstdint>

#define B 128
#define L 200
#define D 256
#define V_SIZE 50000
#define THREADS 256
#define V4 (V_SIZE / 4)            // 12500 float4 per batch row
#define RPW 25                     // rows per warp (L / 8 warps)

__global__ void __launch_bounds__(THREADS)
fused_batch_kernel(const float* __restrict__ w_es,
                   const float* __restrict__ score_v,
                   const int* __restrict__ x,
                   float* __restrict__ out,
                   int write_tail)
{
    __shared__ __align__(16) float sv[D];
    __shared__ int   xsh[THREADS];
    __shared__ float scores[L];
    __shared__ float redm[8];
    __shared__ float reds[8];

    int b = blockIdx.x;
    int tid = threadIdx.x;
    int wid = tid >> 5;
    int lane = tid & 31;

    sv[tid] = score_v[tid];                         // D == THREADS
    xsh[tid] = (tid < L) ? x[(size_t)b * L + tid] : -1;
    __syncthreads();

    // score_v cached in registers: lane owns float4[lane] and float4[lane+32]
    const float4* sv4 = reinterpret_cast<const float4*>(sv);
    float4 sva = sv4[lane];
    float4 svb = sv4[lane + 32];

    // warp w owns rows [25w, 25w+25); row stride = 64 float4
    const float4* base4 = reinterpret_cast<const float4*>(
        w_es + ((size_t)b * L + (size_t)wid * RPW) * D);
    float4* zp = reinterpret_cast<float4*>(out + (size_t)b * V_SIZE);
    float4 zero4 = make_float4(0.f, 0.f, 0.f, 0.f);

    // ---- main loop: 4 rows per iteration (8 LDG.128 in flight) ----
    //      + 8 interleaved STG.128 zero-stores per iteration
    #pragma unroll
    for (int it = 0; it < 6; it++) {
        float4 a[8];
        #pragma unroll
        for (int r = 0; r < 4; r++) {
            const float4* row = base4 + (size_t)(it * 4 + r) * 64;
            a[2 * r]     = row[lane];
            a[2 * r + 1] = row[lane + 32];
        }
        #pragma unroll
        for (int s = 0; s < 8; s++)
            zp[(it * 8 + s) * THREADS + tid] = zero4;

        float acc[4];
        #pragma unroll
        for (int r = 0; r < 4; r++) {
            float t = a[2 * r].x * sva.x;
            t = fmaf(a[2 * r].y, sva.y, t);
            t = fmaf(a[2 * r].z, sva.z, t);
            t = fmaf(a[2 * r].w, sva.w, t);
            t = fmaf(a[2 * r + 1].x, svb.x, t);
            t = fmaf(a[2 * r + 1].y, svb.y, t);
            t = fmaf(a[2 * r + 1].z, svb.z, t);
            t = fmaf(a[2 * r + 1].w, svb.w, t);
            acc[r] = t;
        }
        #pragma unroll
        for (int r = 0; r < 4; r++) {
            float v = acc[r];
            #pragma unroll
            for (int off = 16; off > 0; off >>= 1)
                v += __shfl_xor_sync(0xFFFFFFFF, v, off);
            if (lane == 0) scores[wid * RPW + it * 4 + r] = v;
        }
    }
    // ---- leftover: row 24 of each warp + remaining 212 zero float4s ----
    {
        const float4* row = base4 + (size_t)24 * 64;
        float4 a0 = row[lane];
        float4 a1 = row[lane + 32];
        int zi = 48 * THREADS + tid;               // 12288 + tid
        if (zi < V4) zp[zi] = zero4;

        float v = a0.x * sva.x;
        v = fmaf(a0.y, sva.y, v);
        v = fmaf(a0.z, sva.z, v);
        v = fmaf(a0.w, sva.w, v);
        v = fmaf(a1.x, svb.x, v);
        v = fmaf(a1.y, svb.y, v);
        v = fmaf(a1.z, svb.z, v);
        v = fmaf(a1.w, svb.w, v);
        #pragma unroll
        for (int off = 16; off > 0; off >>= 1)
            v += __shfl_xor_sync(0xFFFFFFFF, v, off);
        if (lane == 0) scores[wid * RPW + 24] = v;
    }
    __syncthreads();   // scores visible; also orders zero-stores before scatter

    // ---- branchless dedup (last-occurrence wins) ----
    int xv = xsh[tid];
    int last = 1;
    #pragma unroll 8
    for (int l = tid + 1; l < L; l++)
        last &= (xsh[l] != xv);

    // ---- softmax: 2-barrier reductions ----
    float v = (tid < L) ? scores[tid] : -3.402823466e38f;

    float m = v;
    #pragma unroll
    for (int off = 16; off > 0; off >>= 1)
        m = fmaxf(m, __shfl_xor_sync(0xFFFFFFFF, m, off));
    if (lane == 0) redm[wid] = m;
    __syncthreads();
    float mx = redm[0];
    #pragma unroll
    for (int i = 1; i < 8; i++) mx = fmaxf(mx, redm[i]);

    float e = (tid < L) ? __expf(v - mx) : 0.f;
    float s = e;
    #pragma unroll
    for (int off = 16; off > 0; off >>= 1)
        s += __shfl_xor_sync(0xFFFFFFFF, s, off);
    if (lane == 0) reds[wid] = s;
    __syncthreads();
    float tot = reds[0];
    #pragma unroll
    for (int i = 1; i < 8; i++) tot += reds[i];

    float w = e * (1.0f / tot);

    // ---- tail + conflict-free scatter (zeroes ordered by barriers above) ----
    if (tid < L) {
        if (write_tail)
            out[(size_t)B * V_SIZE + (size_t)b * L + tid] = w;
        if (last && (unsigned)xv < V_SIZE)
            out[(size_t)b * V_SIZE + xv] = w;
    }
}

extern "C" void kernel_launch(void* const* d_in, const int* in_sizes, int n_in,
                              void* d_out, int out_size)
{
    const float* w_es = (const float*)d_in[0];
    const float* score_v = (const float*)d_in[1];
    const int* x = (const int*)d_in[2];
    float* out = (float*)d_out;

    int write_tail = (out_size >= B * V_SIZE + B * L) ? 1 : 0;

    fused_batch_kernel<<<B, THREADS>>>(w_es, score_v, x, out, write_tail);
}

// round 17
// speedup vs baseline: 1.1082x; 1.1082x over previous
#include <cuda_runtime.h>
#include <cstdint>

#define B 128
#define L 200
#define D 256
#define V_SIZE 50000
#define THREADS 1024
#define NWARPS 32
#define V4 (V_SIZE / 4)            // 12500 float4 per batch row

__global__ void __launch_bounds__(THREADS, 1)
fused_batch_kernel(const float* __restrict__ w_es,
                   const float* __restrict__ score_v,
                   const int* __restrict__ x,
                   float* __restrict__ out,
                   int write_tail)
{
    __shared__ __align__(16) float sv[D];
    __shared__ int   xsh[256];
    __shared__ float scores[L];
    __shared__ float redm[NWARPS];
    __shared__ float reds[NWARPS];

    int b = blockIdx.x;
    int tid = threadIdx.x;
    int wid = tid >> 5;
    int lane = tid & 31;

    if (tid < D) sv[tid] = score_v[tid];
    if (tid < 256) xsh[tid] = (tid < L) ? x[(size_t)b * L + tid] : -1;
    __syncthreads();

    // score_v in registers: lane owns float4[lane] and float4[lane+32]
    const float4* sv4 = reinterpret_cast<const float4*>(sv);
    float4 sva = sv4[lane];
    float4 svb = sv4[lane + 32];

    // warp w owns rows {w, w+32, ...}: 7 rows for w<8, else 6  (8*7+24*6=200)
    const float4* base4 = reinterpret_cast<const float4*>(w_es)
                        + ((size_t)b * L + (size_t)wid) * 64;
    float4* zp = reinterpret_cast<float4*>(out + (size_t)b * V_SIZE);
    float4 zero4 = make_float4(0.f, 0.f, 0.f, 0.f);

    // ---- phase 1: front-load rows k=0..3 (8 LDG.128 in flight/warp) ----
    float4 a[8];
    #pragma unroll
    for (int k = 0; k < 4; k++) {
        const float4* row = base4 + (size_t)k * 32 * 64;
        a[2 * k]     = row[lane];
        a[2 * k + 1] = row[lane + 32];
    }
    // interleave first half of the zero-fill (6 STG.128/thread)
    #pragma unroll
    for (int s = 0; s < 6; s++)
        zp[s * THREADS + tid] = zero4;

    #pragma unroll
    for (int k = 0; k < 4; k++) {
        float t = a[2 * k].x * sva.x;
        t = fmaf(a[2 * k].y, sva.y, t);
        t = fmaf(a[2 * k].z, sva.z, t);
        t = fmaf(a[2 * k].w, sva.w, t);
        t = fmaf(a[2 * k + 1].x, svb.x, t);
        t = fmaf(a[2 * k + 1].y, svb.y, t);
        t = fmaf(a[2 * k + 1].z, svb.z, t);
        t = fmaf(a[2 * k + 1].w, svb.w, t);
        #pragma unroll
        for (int off = 16; off > 0; off >>= 1)
            t += __shfl_xor_sync(0xFFFFFFFF, t, off);
        if (lane == 0) scores[wid + 32 * k] = t;
    }

    // ---- phase 2: rows k=4,5 (+6 for wid<8) + rest of zero-fill ----
    float4 c[6];
    #pragma unroll
    for (int k = 0; k < 2; k++) {
        const float4* row = base4 + (size_t)(4 + k) * 32 * 64;
        c[2 * k]     = row[lane];
        c[2 * k + 1] = row[lane + 32];
    }
    bool has7 = (wid < 8);
    if (has7) {
        const float4* row = base4 + (size_t)6 * 32 * 64;
        c[4] = row[lane];
        c[5] = row[lane + 32];
    }
    #pragma unroll
    for (int s = 6; s < 12; s++)
        zp[s * THREADS + tid] = zero4;
    if (12 * THREADS + tid < V4)               // 12288..12499
        zp[12 * THREADS + tid] = zero4;

    #pragma unroll
    for (int k = 0; k < 2; k++) {
        float t = c[2 * k].x * sva.x;
        t = fmaf(c[2 * k].y, sva.y, t);
        t = fmaf(c[2 * k].z, sva.z, t);
        t = fmaf(c[2 * k].w, sva.w, t);
        t = fmaf(c[2 * k + 1].x, svb.x, t);
        t = fmaf(c[2 * k + 1].y, svb.y, t);
        t = fmaf(c[2 * k + 1].z, svb.z, t);
        t = fmaf(c[2 * k + 1].w, svb.w, t);
        #pragma unroll
        for (int off = 16; off > 0; off >>= 1)
            t += __shfl_xor_sync(0xFFFFFFFF, t, off);
        if (lane == 0) scores[wid + 32 * (4 + k)] = t;
    }
    if (has7) {
        float t = c[4].x * sva.x;
        t = fmaf(c[4].y, sva.y, t);
        t = fmaf(c[4].z, sva.z, t);
        t = fmaf(c[4].w, sva.w, t);
        t = fmaf(c[5].x, svb.x, t);
        t = fmaf(c[5].y, svb.y, t);
        t = fmaf(c[5].z, svb.z, t);
        t = fmaf(c[5].w, svb.w, t);
        #pragma unroll
        for (int off = 16; off > 0; off >>= 1)
            t += __shfl_xor_sync(0xFFFFFFFF, t, off);
        if (lane == 0) scores[wid + 192] = t;
    }

    __syncthreads();   // scores visible; orders zero-stores before scatter

    // ---- branchless dedup (last-occurrence wins), threads 0..199 ----
    int xv = (tid < 256) ? xsh[tid & 255] : -1;
    int last = 1;
    if (tid < L) {
        #pragma unroll 8
        for (int l = tid + 1; l < L; l++)
            last &= (xsh[l] != xv);
    }

    // ---- softmax: uniform 2-barrier reductions over all 32 warps ----
    float v = (tid < L) ? scores[tid] : -3.402823466e38f;

    float m = v;
    #pragma unroll
    for (int off = 16; off > 0; off >>= 1)
        m = fmaxf(m, __shfl_xor_sync(0xFFFFFFFF, m, off));
    if (lane == 0) redm[wid] = m;
    __syncthreads();
    float mx = redm[0];
    #pragma unroll
    for (int i = 1; i < NWARPS; i++) mx = fmaxf(mx, redm[i]);

    float e = (tid < L) ? __expf(v - mx) : 0.f;
    float s = e;
    #pragma unroll
    for (int off = 16; off > 0; off >>= 1)
        s += __shfl_xor_sync(0xFFFFFFFF, s, off);
    if (lane == 0) reds[wid] = s;
    __syncthreads();
    float tot = reds[0];
    #pragma unroll
    for (int i = 1; i < NWARPS; i++) tot += reds[i];

    float w = e * (1.0f / tot);

    // ---- tail + conflict-free scatter ----
    if (tid < L) {
        if (write_tail)
            out[(size_t)B * V_SIZE + (size_t)b * L + tid] = w;
        if (last && (unsigned)xv < V_SIZE)
            out[(size_t)b * V_SIZE + xv] = w;
    }
}

extern "C" void kernel_launch(void* const* d_in, const int* in_sizes, int n_in,
                              void* d_out, int out_size)
{
    const float* w_es = (const float*)d_in[0];
    const float* score_v = (const float*)d_in[1];
    const int* x = (const int*)d_in[2];
    float* out = (float*)d_out;

    int write_tail = (out_size >= B * V_SIZE + B * L) ? 1 : 0;

    fused_batch_kernel<<<B, THREADS>>>(w_es, score_v, x, out, write_tail);
}